// round 16
// baseline (speedup 1.0000x reference)
#include <cuda_runtime.h>
#include <cuda_fp16.h>
#include <mma.h>
#include <math.h>

using namespace nvcuda;

#define D  64
#define L  50
#define NU 30000
#define NI 20000
#define NT (NU + NI)        // 50000 total nodes
#define KMP 192             // padded m-vector: 64 hl | 64 hs | 50 beta | 14 zero

#define QN   64
#define NBI  ((NI + QN - 1) / QN)   // 313
#define NBU  ((NU + QN - 1) / QN)   // 469
#define PBI  ((NI + 63) / 64)       // 313
#define PBU  ((NU + 63) / 64)       // 469
#define PB   (PBU + PBI)
#define QB   (NBI + NBU)
#define EIB  ((NI + 63) / 64)       // 313 epilogue item blocks (64 nodes each)
#define EUB  ((NU + 63) / 64)       // 469 epilogue user blocks

// device scratch (allocation-free rule; statically zero-initialized)
__device__ __half g_uh[NU * D];
__device__ __half g_ih[NI * D];
__device__ float  g_q[NT * L];              // q[n][r] = dot(te[r], h_n)
__device__ __half g_m[(NT + 64) * KMP];     // per-node m vector (fp16, padded)
__device__ __half g_wch[2][KMP * D];        // fp16 Wcat: [Wg ; te_k@Wg_top ; 0]
__device__ float  g_teW[2][L * D];          // te @ W^T per side

// ---------------------------------------------------------------------------
// prep: blocks 0,1 -> Wcat(half); blocks 2,3 -> teW = te @ W^T
// ---------------------------------------------------------------------------
__global__ __launch_bounds__(256) void prep(
    const float* __restrict__ Wg_i, const float* __restrict__ i_te_k,
    const float* __restrict__ Wg_u, const float* __restrict__ u_te_k,
    const float* __restrict__ i_te, const float* __restrict__ u_te,
    const float* __restrict__ W_i,  const float* __restrict__ W_u)
{
    const int t = threadIdx.x;
    __shared__ float Wsh[D * D];

    if (blockIdx.x < 2) {           // Wcat (fp16)
        const int s = blockIdx.x;   // 0 item, 1 user
        const float* Wg   = s == 0 ? Wg_i : Wg_u;
        const float* te_k = s == 0 ? i_te_k : u_te_k;
        __half* out = g_wch[s];
        for (int idx = t; idx < D * D; idx += 256) Wsh[idx] = Wg[idx];
        for (int idx = t; idx < 2 * D * D; idx += 256)
            out[idx] = __float2half(Wg[idx]);               // rows 0..127
        for (int idx = t; idx < (KMP - 2 * D - L) * D; idx += 256)
            out[(2 * D + L) * D + idx] = __half(0.f);       // rows 178..191
        __syncthreads();
        for (int idx = t; idx < L * D; idx += 256) {        // rows 128..177
            const int r = idx >> 6, c = idx & 63;
            float acc = 0.f;
#pragma unroll 8
            for (int d = 0; d < D; d++) acc += te_k[r * D + d] * Wsh[d * D + c];
            out[(2 * D + r) * D + c] = __float2half(acc);
        }
    } else {                        // teW[r][k] = sum_d te[r,d] * W[k,d]
        const int s = blockIdx.x - 2;
        const float* te = s == 0 ? i_te : u_te;
        const float* W  = s == 0 ? W_i  : W_u;
        float* out = g_teW[s];
        for (int idx = t; idx < D * D; idx += 256) Wsh[idx] = W[idx];
        __syncthreads();
        for (int idx = t; idx < L * D; idx += 256) {
            const int r = idx >> 6, k = idx & 63;
            float acc = 0.f;
#pragma unroll 8
            for (int d = 0; d < D; d++) acc += te[r * D + d] * Wsh[k * D + d];
            out[r * D + k] = acc;
        }
    }
}

// ---------------------------------------------------------------------------
// projq: fused SIMT. [0,PB): proj (W read from L1-hot global, fT-only smem
// -> 17.4KB -> single wave); [PB,+QB): q GEMM (R13 exact)
// ---------------------------------------------------------------------------
union SmemPQ {
    struct { float  fT[D * 68]; } p;
    struct { __half hT[D][68];  __half tT[D][56]; } q;
};

__global__ __launch_bounds__(256) void projq(
    const float* __restrict__ user_feat, const float* __restrict__ item_feat,
    const float* __restrict__ W_u,       const float* __restrict__ W_i)
{
    __shared__ SmemPQ sm;
    const int t = threadIdx.x, lane = t & 31, w = t >> 5;

    if (blockIdx.x < PB) {
        // ---------------- proj path ----------------
        const bool user = blockIdx.x < PBU;
        const int  r0   = (user ? blockIdx.x : blockIdx.x - PBU) * 64;
        const int  N    = user ? NU : NI;
        const float* feat = user ? user_feat : item_feat;
        const float* W    = user ? W_u : W_i;
        __half* outp      = user ? g_uh : g_ih;

#pragma unroll
        for (int i = 0; i < 8; i++) {
            const int r = w * 8 + i, row = r0 + r;
            float a = 0.f, b = 0.f;
            if (row < N) { a = feat[row * D + lane]; b = feat[row * D + 32 + lane]; }
            sm.p.fT[lane * 68 + r]        = a;
            sm.p.fT[(32 + lane) * 68 + r] = b;
        }
        __syncthreads();

        const int rg = t >> 4, cg = t & 15;
        float acc[4][4];
#pragma unroll
        for (int i = 0; i < 4; i++)
#pragma unroll
            for (int j = 0; j < 4; j++) acc[i][j] = 0.f;
#pragma unroll 8
        for (int k = 0; k < D; k++) {
            const float4 fv = *(const float4*)&sm.p.fT[k * 68 + rg * 4];
            const float4 wv = *(const float4*)&W[k * D + cg * 4];   // L1-hot
            const float f[4]  = {fv.x, fv.y, fv.z, fv.w};
            const float wc[4] = {wv.x, wv.y, wv.z, wv.w};
#pragma unroll
            for (int i = 0; i < 4; i++)
#pragma unroll
                for (int j = 0; j < 4; j++) acc[i][j] += f[i] * wc[j];
        }
#pragma unroll
        for (int i = 0; i < 4; i++) {
            const int row = r0 + rg * 4 + i;
            if (row < N) {
                __half2 p0 = __floats2half2_rn(acc[i][0], acc[i][1]);
                __half2 p1 = __floats2half2_rn(acc[i][2], acc[i][3]);
                *(__half2*)&outp[row * D + cg * 4]     = p0;
                *(__half2*)&outp[row * D + cg * 4 + 2] = p1;
            }
        }
    } else {
        // ---------------- q path ----------------
        const int  qb   = blockIdx.x - PB;
        const bool item = qb < NBI;
        const int  n0   = (item ? qb : qb - NBI) * QN;
        const int  N    = item ? NI : NU;
        const float* feat = item ? item_feat : user_feat;
        const float* teW  = g_teW[item ? 0 : 1];
        float* qout       = g_q + (item ? 0 : NI * L);

        for (int j = w; j < QN; j += 8) {
            const int n = n0 + j;
            float a = 0.f, b = 0.f;
            if (n < N) { a = feat[n * D + lane]; b = feat[n * D + 32 + lane]; }
            sm.q.hT[lane][j]      = __float2half(a);
            sm.q.hT[32 + lane][j] = __float2half(b);
        }
        for (int r = w; r < 52; r += 8) {
            float a = 0.f, b = 0.f;
            if (r < L) { a = teW[r * D + lane]; b = teW[r * D + 32 + lane]; }
            sm.q.tT[lane][r]      = __float2half(a);
            sm.q.tT[32 + lane][r] = __float2half(b);
        }
        __syncthreads();

        if (t < 208) {
            const int nb = (t & 15) * 4;
            const int rb = (t >> 4) * 4;
            float acc[4][4];
#pragma unroll
            for (int i = 0; i < 4; i++)
#pragma unroll
                for (int j = 0; j < 4; j++) acc[i][j] = 0.f;
#pragma unroll
            for (int d = 0; d < D; d++) {
                const __half2 ha = *(const __half2*)&sm.q.hT[d][nb];
                const __half2 hb = *(const __half2*)&sm.q.hT[d][nb + 2];
                const __half2 ta = *(const __half2*)&sm.q.tT[d][rb];
                const __half2 tb = *(const __half2*)&sm.q.tT[d][rb + 2];
                const float h0 = __low2float(ha), h1 = __high2float(ha);
                const float h2 = __low2float(hb), h3 = __high2float(hb);
                const float t0 = __low2float(ta), t1 = __high2float(ta);
                const float t2 = __low2float(tb), t3 = __high2float(tb);
                acc[0][0] += h0 * t0; acc[0][1] += h0 * t1; acc[0][2] += h0 * t2; acc[0][3] += h0 * t3;
                acc[1][0] += h1 * t0; acc[1][1] += h1 * t1; acc[1][2] += h1 * t2; acc[1][3] += h1 * t3;
                acc[2][0] += h2 * t0; acc[2][1] += h2 * t1; acc[2][2] += h2 * t2; acc[2][3] += h2 * t3;
                acc[3][0] += h3 * t0; acc[3][1] += h3 * t1; acc[3][2] += h3 * t2; acc[3][3] += h3 * t3;
            }
#pragma unroll
            for (int i = 0; i < 4; i++) {
                const int n = n0 + nb + i;
                if (n < N) {
#pragma unroll
                    for (int j = 0; j < 4; j++)
                        if (rb + j < L) qout[n * L + rb + j] = acc[i][j];
                }
            }
        }
    }
}

// ---------------------------------------------------------------------------
// attn_all (R13 exact): uint2 gather + packed-key ranks + hfma2 logits
//   (q prefetched to shared) + warp0 softmax + warp0 half2 weighted sums
// ---------------------------------------------------------------------------
#define MBP 72

__global__ __launch_bounds__(64) void attn_all(
    const int* __restrict__ item_nbr, const int* __restrict__ item_time,
    const int* __restrict__ user_nbr, const int* __restrict__ user_time)
{
    const int b    = blockIdx.x;
    const int tid  = threadIdx.x;
    const int lane = tid & 31;
    const int wid  = tid >> 5;

    int n;
    const __half *src_h, *dst_h;
    const int *nbr, *tim;
    if (b < NI) {
        n = b;  src_h = g_uh;  dst_h = g_ih;
        nbr = item_nbr;  tim = item_time;
    } else {
        n = b - NI;  src_h = g_ih;  dst_h = g_uh;
        nbr = user_nbr;  tim = user_time;
    }
    const float* qrow = g_q + b * L;
    __half* mrow = g_m + b * KMP;

    __shared__ __align__(16) __half mb[L][MBP];
    __shared__ __align__(16) __half hh[D];
    __shared__ __align__(16) int    ks[64];     // packed keys: time*64 + idx
    __shared__ float   qs[L];                   // prefetched q row
    __shared__ float   ee[L], e1[L];
    __shared__ __half2 eep[L], e1p[L];          // duplicated-alpha pairs
    __shared__ int     nbs[L], ro[L];
    __shared__ int     s_last;

    if (tid < 32) ((__half2*)hh)[tid] = ((const __half2*)(dst_h + n * D))[tid];
    if (tid < L) {
        ks[tid]  = tim[n * L + tid] * 64 + tid;
        nbs[tid] = nbr[n * L + tid];
        qs[tid]  = qrow[tid];                   // hide L2 latency under gather
    } else {
        ks[tid] = 0x7fffffff;                   // pad: counts as >= any key
    }
    __syncthreads();

    // gather mailbox (8B loads, 8B stores, 4 rows per pass; MLP=13)
    {
        const int lane4 = tid & 15, row4 = tid >> 4;
#pragma unroll
        for (int l0 = 0; l0 < 48; l0 += 4) {
            const int l = l0 + row4;
            const uint2 val = *((const uint2*)(src_h + nbs[l] * D) + lane4);
            *(uint2*)&mb[l][lane4 * 4] = val;
        }
        if (row4 < 2) {
            const int l = 48 + row4;
            const uint2 val = *((const uint2*)(src_h + nbs[l] * D) + lane4);
            *(uint2*)&mb[l][lane4 * 4] = val;
        }
    }

    // ranks: packed keys, strict < == stable (time, idx) order
    if (tid < L) {
        const int k = ks[tid];
        int r = 0;
#pragma unroll
        for (int jb = 0; jb < 13; jb++) {
            const int4 v = ((const int4*)ks)[jb];
            r += (v.x < k) + (v.y < k) + (v.z < k) + (v.w < k);
        }
        ro[tid] = L - 1 - r;
    }
    // argmax (first index of max): max of key^63 flips tie-break to lowest idx
    if (wid == 0) {
        int bv = ks[lane] ^ 63;
        if (lane < L - 32) bv = max(bv, ks[lane + 32] ^ 63);
#pragma unroll
        for (int o = 16; o > 0; o >>= 1)
            bv = max(bv, __shfl_xor_sync(0xffffffffu, bv, o));
        if (lane == 0) s_last = (bv & 63) ^ 63;
    }
    __syncthreads();

    // logits: hfma2 on 16B LDS rows
    if (tid < L) {
        const uint4* rowp  = (const uint4*)&mb[tid][0];
        const uint4* lastp = (const uint4*)&mb[s_last][0];
        const uint4* hp    = (const uint4*)hh;
        __half2 sa = __float2half2_rn(0.f), sb = sa, ta = sa, tb = sa;
#pragma unroll
        for (int i = 0; i < 8; i++) {
            const uint4 rv = rowp[i], lv = lastp[i], hv = hp[i];
            const __half2 r0 = *(const __half2*)&rv.x, r1 = *(const __half2*)&rv.y;
            const __half2 r2 = *(const __half2*)&rv.z, r3 = *(const __half2*)&rv.w;
            const __half2 l0 = *(const __half2*)&lv.x, l1 = *(const __half2*)&lv.y;
            const __half2 l2 = *(const __half2*)&lv.z, l3 = *(const __half2*)&lv.w;
            const __half2 h0 = *(const __half2*)&hv.x, h1 = *(const __half2*)&hv.y;
            const __half2 h2 = *(const __half2*)&hv.z, h3 = *(const __half2*)&hv.w;
            sa = __hfma2(r0, h0, sa); sb = __hfma2(r1, h1, sb);
            sa = __hfma2(r2, h2, sa); sb = __hfma2(r3, h3, sb);
            ta = __hfma2(r0, l0, ta); tb = __hfma2(r1, l1, tb);
            ta = __hfma2(r2, l2, ta); tb = __hfma2(r3, l3, tb);
        }
        const float s  = __low2float(sa) + __high2float(sa)
                       + __low2float(sb) + __high2float(sb);
        const float s1 = __low2float(ta) + __high2float(ta)
                       + __low2float(tb) + __high2float(tb);
        ee[tid] = (s + qs[ro[tid]]) * 0.125f;
        e1[tid] = s1 * 0.125f;
    }
    __syncthreads();

    // two softmaxes over L (warp 0); emit duplicated half2 alphas
    if (wid == 0) {
        float m = -1e30f, m1 = -1e30f;
        for (int l = lane; l < L; l += 32) {
            m  = fmaxf(m,  ee[l]);
            m1 = fmaxf(m1, e1[l]);
        }
#pragma unroll
        for (int o = 16; o > 0; o >>= 1) {
            m  = fmaxf(m,  __shfl_xor_sync(0xffffffffu, m,  o));
            m1 = fmaxf(m1, __shfl_xor_sync(0xffffffffu, m1, o));
        }
        float s = 0.f, s1 = 0.f;
        for (int l = lane; l < L; l += 32) {
            const float a  = __expf(ee[l] - m);
            const float a1 = __expf(e1[l] - m1);
            ee[l] = a;  e1[l] = a1;
            s += a;  s1 += a1;
        }
#pragma unroll
        for (int o = 16; o > 0; o >>= 1) {
            s  += __shfl_xor_sync(0xffffffffu, s,  o);
            s1 += __shfl_xor_sync(0xffffffffu, s1, o);
        }
        const float inv = 1.f / s, inv1 = 1.f / s1;
        for (int l = lane; l < L; l += 32) {
            const float a  = ee[l] * inv;
            const float a1 = e1[l] * inv1;
            ee[l] = a;
            eep[l] = __half2half2(__float2half(a));
            e1p[l] = __half2half2(__float2half(a1));
        }
    }
    __syncthreads();

    // weighted mailbox sums: warp0, half2, 2 cols/thread, dual accumulators
    if (tid < 32) {
        __half2 al0 = __float2half2_rn(0.f), al1 = al0, as0 = al0, as1 = al0;
#pragma unroll
        for (int l = 0; l < L; l += 2) {
            const __half2 m0 = *(const __half2*)&mb[l][2 * tid];
            al0 = __hfma2(eep[l], m0, al0);
            as0 = __hfma2(e1p[l], m0, as0);
            const __half2 m1 = *(const __half2*)&mb[l + 1][2 * tid];
            al1 = __hfma2(eep[l + 1], m1, al1);
            as1 = __hfma2(e1p[l + 1], m1, as1);
        }
        *(__half2*)&mrow[2 * tid]     = __hadd2(al0, al1);
        *(__half2*)&mrow[D + 2 * tid] = __hadd2(as0, as1);
    }
    if (tid < L) mrow[2 * D + ro[tid]] = __float2half(ee[tid]);
    else         mrow[2 * D + tid]     = __half(0.f);   // pad 178..191
}

// ---------------------------------------------------------------------------
// epilogue (HMMA): out = elu(m(fp16) @ Wcat(fp16) + feat).
// 64 nodes x 64 cols per 128-thread block; warp w -> row tile w, 4 col-tile
// accumulators (4 independent HMMA chains). As/ot unioned (26.6KB).
// ---------------------------------------------------------------------------
#define ASTR 208   // smem A row stride in halves (416B, 16B-aligned)

__global__ __launch_bounds__(128) void epilogue(
    const float* __restrict__ user_feat, const float* __restrict__ item_feat,
    float* __restrict__ user_out,        float* __restrict__ item_out)
{
    const bool item = blockIdx.x < EIB;
    const int  nb   = item ? blockIdx.x * 64 : NI + (blockIdx.x - EIB) * 64;
    const __half* Wc  = g_wch[item ? 0 : 1];
    const float* feat = item ? item_feat : user_feat;
    float* out        = item ? item_out  : user_out;
    const int base    = item ? nb : nb - NI;
    const int Nloc    = item ? NI : NU;

    // As (64*ASTR halves = 26624B) and ot (64*72 floats = 18432B) share storage
    __shared__ __align__(16) char smem_buf[64 * ASTR * sizeof(__half)];
    __half* As = (__half*)smem_buf;
    float*  ot = (float*)smem_buf;

    const int t = threadIdx.x, w = t >> 5;   // 4 warps: row tile w

    // stage 64x192 A tile (g_m rows nb..nb+63; pad rows zero-initialized)
    {
        const __half* asrc = g_m + (size_t)nb * KMP;
#pragma unroll
        for (int i = t; i < 64 * (KMP / 8); i += 128) {
            const int row = i / (KMP / 8), c8 = i % (KMP / 8);
            *(float4*)&As[row * ASTR + c8 * 8] =
                *(const float4*)&asrc[row * KMP + c8 * 8];
        }
    }
    __syncthreads();

    wmma::fragment<wmma::accumulator, 16, 16, 16, float> acc[4];
#pragma unroll
    for (int c = 0; c < 4; c++) wmma::fill_fragment(acc[c], 0.f);

#pragma unroll
    for (int kt = 0; kt < KMP / 16; kt++) {
        wmma::fragment<wmma::matrix_a, 16, 16, 16, __half, wmma::row_major> af;
        wmma::load_matrix_sync(af, &As[(w * 16) * ASTR + kt * 16], ASTR);
#pragma unroll
        for (int ct = 0; ct < 4; ct++) {
            wmma::fragment<wmma::matrix_b, 16, 16, 16, __half, wmma::row_major> bf;
            wmma::load_matrix_sync(bf, Wc + kt * 16 * D + ct * 16, D);
            wmma::mma_sync(acc[ct], af, bf, acc[ct]);
        }
    }
    __syncthreads();   // ALL warps done reading As before ot overwrites it
#pragma unroll
    for (int ct = 0; ct < 4; ct++)
        wmma::store_matrix_sync(&ot[(w * 16) * 72 + ct * 16], acc[ct],
                                72, wmma::mem_row_major);
    __syncthreads();

    // residual + ELU (64 rows x 64 cols / 128 threads = 8 float4 each)
    const int col = (t & 15) * 4, r0 = t >> 4;   // r0: 0..7
#pragma unroll
    for (int i = 0; i < 8; i++) {
        const int row = r0 + i * 8;
        const int nl  = base + row;
        if (nl < Nloc) {
            const float4 fv = *(const float4*)&feat[nl * D + col];
            const float4 av = *(const float4*)&ot[row * 72 + col];
            float4 r;
            r.x = av.x + fv.x;  r.x = r.x > 0.f ? r.x : expm1f(r.x);
            r.y = av.y + fv.y;  r.y = r.y > 0.f ? r.y : expm1f(r.y);
            r.z = av.z + fv.z;  r.z = r.z > 0.f ? r.z : expm1f(r.z);
            r.w = av.w + fv.w;  r.w = r.w > 0.f ? r.w : expm1f(r.w);
            *(float4*)&out[nl * D + col] = r;
        }
    }
}

// ---------------------------------------------------------------------------
extern "C" void kernel_launch(void* const* d_in, const int* in_sizes, int n_in,
                              void* d_out, int out_size) {
    const float* user_feat = (const float*)d_in[0];
    const float* item_feat = (const float*)d_in[1];
    const float* W_u       = (const float*)d_in[2];
    const float* W_i       = (const float*)d_in[3];
    const float* Wg_u      = (const float*)d_in[4];
    const float* Wg_i      = (const float*)d_in[5];
    const float* i_te      = (const float*)d_in[6];
    const float* i_te_k    = (const float*)d_in[7];
    const float* u_te      = (const float*)d_in[8];
    const float* u_te_k    = (const float*)d_in[9];
    const int*   item_nbr  = (const int*)d_in[10];
    const int*   item_time = (const int*)d_in[11];
    const int*   user_nbr  = (const int*)d_in[12];
    const int*   user_time = (const int*)d_in[13];

    float* user_out = (float*)d_out;            // [NU, D]
    float* item_out = (float*)d_out + NU * D;   // [NI, D]

    prep<<<4, 256>>>(Wg_i, i_te_k, Wg_u, u_te_k, i_te, u_te, W_i, W_u);
    projq<<<PB + QB, 256>>>(user_feat, item_feat, W_u, W_i);
    attn_all<<<NT, 64>>>(item_nbr, item_time, user_nbr, user_time);
    epilogue<<<EIB + EUB, 128>>>(user_feat, item_feat, user_out, item_out);
}

// round 17
// speedup vs baseline: 1.1332x; 1.1332x over previous
#include <cuda_runtime.h>
#include <cuda_fp16.h>
#include <mma.h>
#include <math.h>

using namespace nvcuda;

#define D  64
#define L  50
#define NU 30000
#define NI 20000
#define NT (NU + NI)        // 50000 total nodes
#define KMP 192             // padded m-vector: 64 hl | 64 hs | 50 beta | 14 zero

#define QN   64
#define NBI  ((NI + QN - 1) / QN)   // 313
#define NBU  ((NU + QN - 1) / QN)   // 469
#define PBI  ((NI + 63) / 64)       // 313
#define PBU  ((NU + 63) / 64)       // 469
#define PB   (PBU + PBI)
#define QB   (NBI + NBU)
#define EIB  ((NI + 31) / 32)       // 625 epilogue item blocks (32 nodes each)
#define EUB  ((NU + 31) / 32)       // 938 epilogue user blocks

// device scratch (allocation-free rule; statically zero-initialized)
__device__ __half g_uh[NU * D];
__device__ __half g_ih[NI * D];
__device__ float  g_q[NT * L];              // q[n][r] = dot(te[r], h_n)
__device__ __half g_m[(NT + 64) * KMP];     // per-node m vector (fp16, padded)
__device__ __half g_wch[2][KMP * D];        // fp16 Wcat: [Wg ; te_k@Wg_top ; 0]
__device__ float  g_teW[2][L * D];          // te @ W^T per side

// ---------------------------------------------------------------------------
// prep (16 blocks): b<8 -> Wcat (s=b>>2, part=b&3); b>=8 -> teW likewise.
// Each part strides a virtual 1024-thread block -> 4x shorter serial tail.
// ---------------------------------------------------------------------------
__global__ __launch_bounds__(256) void prep(
    const float* __restrict__ Wg_i, const float* __restrict__ i_te_k,
    const float* __restrict__ Wg_u, const float* __restrict__ u_te_k,
    const float* __restrict__ i_te, const float* __restrict__ u_te,
    const float* __restrict__ W_i,  const float* __restrict__ W_u)
{
    const int b  = blockIdx.x;
    const int tt = (b & 3) * 256 + threadIdx.x;   // virtual tid in 0..1023
    const int t  = threadIdx.x;
    __shared__ float Wsh[D * D];

    if (b < 8) {                    // Wcat (fp16)
        const int s = b >> 2;       // 0 item, 1 user
        const float* Wg   = s == 0 ? Wg_i : Wg_u;
        const float* te_k = s == 0 ? i_te_k : u_te_k;
        __half* out = g_wch[s];
        for (int idx = t; idx < D * D; idx += 256) Wsh[idx] = Wg[idx];
        for (int idx = tt; idx < 2 * D * D; idx += 1024)
            out[idx] = __float2half(Wg[idx]);               // rows 0..127
        for (int idx = tt; idx < (KMP - 2 * D - L) * D; idx += 1024)
            out[(2 * D + L) * D + idx] = __half(0.f);       // rows 178..191
        __syncthreads();
        for (int idx = tt; idx < L * D; idx += 1024) {      // rows 128..177
            const int r = idx >> 6, c = idx & 63;
            float acc = 0.f;
#pragma unroll 8
            for (int d = 0; d < D; d++) acc += te_k[r * D + d] * Wsh[d * D + c];
            out[(2 * D + r) * D + c] = __float2half(acc);
        }
    } else {                        // teW[r][k] = sum_d te[r,d] * W[k,d]
        const int s = (b - 8) >> 2;
        const float* te = s == 0 ? i_te : u_te;
        const float* W  = s == 0 ? W_i  : W_u;
        float* out = g_teW[s];
        for (int idx = t; idx < D * D; idx += 256) Wsh[idx] = W[idx];
        __syncthreads();
        for (int idx = tt; idx < L * D; idx += 1024) {
            const int r = idx >> 6, k = idx & 63;
            float acc = 0.f;
#pragma unroll 8
            for (int d = 0; d < D; d++) acc += te[r * D + d] * Wsh[k * D + d];
            out[r * D + k] = acc;
        }
    }
}

// ---------------------------------------------------------------------------
// projq (R15 exact): fused SIMT. [0,PB): proj fp32 staging; [PB,+QB): q GEMM
// ---------------------------------------------------------------------------
union SmemPQ {
    struct { float  fT[D * 68]; float  Ws[D * 68]; } p;
    struct { __half hT[D][68];  __half tT[D][56];  } q;
};

__global__ __launch_bounds__(256) void projq(
    const float* __restrict__ user_feat, const float* __restrict__ item_feat,
    const float* __restrict__ W_u,       const float* __restrict__ W_i)
{
    __shared__ SmemPQ sm;
    const int t = threadIdx.x, lane = t & 31, w = t >> 5;

    if (blockIdx.x < PB) {
        // ---------------- proj path ----------------
        const bool user = blockIdx.x < PBU;
        const int  r0   = (user ? blockIdx.x : blockIdx.x - PBU) * 64;
        const int  N    = user ? NU : NI;
        const float* feat = user ? user_feat : item_feat;
        const float* W    = user ? W_u : W_i;
        __half* outp      = user ? g_uh : g_ih;

#pragma unroll
        for (int i = 0; i < 8; i++) {
            const int r = w * 8 + i, row = r0 + r;
            float a = 0.f, b = 0.f;
            if (row < N) { a = feat[row * D + lane]; b = feat[row * D + 32 + lane]; }
            sm.p.fT[lane * 68 + r]        = a;
            sm.p.fT[(32 + lane) * 68 + r] = b;
        }
        for (int idx = t; idx < D * D; idx += 256)
            sm.p.Ws[(idx >> 6) * 68 + (idx & 63)] = W[idx];
        __syncthreads();

        const int rg = t >> 4, cg = t & 15;
        float acc[4][4];
#pragma unroll
        for (int i = 0; i < 4; i++)
#pragma unroll
            for (int j = 0; j < 4; j++) acc[i][j] = 0.f;
#pragma unroll 8
        for (int k = 0; k < D; k++) {
            const float4 fv = *(const float4*)&sm.p.fT[k * 68 + rg * 4];
            const float4 wv = *(const float4*)&sm.p.Ws[k * 68 + cg * 4];
            const float f[4]  = {fv.x, fv.y, fv.z, fv.w};
            const float wc[4] = {wv.x, wv.y, wv.z, wv.w};
#pragma unroll
            for (int i = 0; i < 4; i++)
#pragma unroll
                for (int j = 0; j < 4; j++) acc[i][j] += f[i] * wc[j];
        }
#pragma unroll
        for (int i = 0; i < 4; i++) {
            const int row = r0 + rg * 4 + i;
            if (row < N) {
                __half2 p0 = __floats2half2_rn(acc[i][0], acc[i][1]);
                __half2 p1 = __floats2half2_rn(acc[i][2], acc[i][3]);
                *(__half2*)&outp[row * D + cg * 4]     = p0;
                *(__half2*)&outp[row * D + cg * 4 + 2] = p1;
            }
        }
    } else {
        // ---------------- q path ----------------
        const int  qb   = blockIdx.x - PB;
        const bool item = qb < NBI;
        const int  n0   = (item ? qb : qb - NBI) * QN;
        const int  N    = item ? NI : NU;
        const float* feat = item ? item_feat : user_feat;
        const float* teW  = g_teW[item ? 0 : 1];
        float* qout       = g_q + (item ? 0 : NI * L);

        for (int j = w; j < QN; j += 8) {
            const int n = n0 + j;
            float a = 0.f, b = 0.f;
            if (n < N) { a = feat[n * D + lane]; b = feat[n * D + 32 + lane]; }
            sm.q.hT[lane][j]      = __float2half(a);
            sm.q.hT[32 + lane][j] = __float2half(b);
        }
        for (int r = w; r < 52; r += 8) {
            float a = 0.f, b = 0.f;
            if (r < L) { a = teW[r * D + lane]; b = teW[r * D + 32 + lane]; }
            sm.q.tT[lane][r]      = __float2half(a);
            sm.q.tT[32 + lane][r] = __float2half(b);
        }
        __syncthreads();

        if (t < 208) {
            const int nb = (t & 15) * 4;
            const int rb = (t >> 4) * 4;
            float acc[4][4];
#pragma unroll
            for (int i = 0; i < 4; i++)
#pragma unroll
                for (int j = 0; j < 4; j++) acc[i][j] = 0.f;
#pragma unroll
            for (int d = 0; d < D; d++) {
                const __half2 ha = *(const __half2*)&sm.q.hT[d][nb];
                const __half2 hb = *(const __half2*)&sm.q.hT[d][nb + 2];
                const __half2 ta = *(const __half2*)&sm.q.tT[d][rb];
                const __half2 tb = *(const __half2*)&sm.q.tT[d][rb + 2];
                const float h0 = __low2float(ha), h1 = __high2float(ha);
                const float h2 = __low2float(hb), h3 = __high2float(hb);
                const float t0 = __low2float(ta), t1 = __high2float(ta);
                const float t2 = __low2float(tb), t3 = __high2float(tb);
                acc[0][0] += h0 * t0; acc[0][1] += h0 * t1; acc[0][2] += h0 * t2; acc[0][3] += h0 * t3;
                acc[1][0] += h1 * t0; acc[1][1] += h1 * t1; acc[1][2] += h1 * t2; acc[1][3] += h1 * t3;
                acc[2][0] += h2 * t0; acc[2][1] += h2 * t1; acc[2][2] += h2 * t2; acc[2][3] += h2 * t3;
                acc[3][0] += h3 * t0; acc[3][1] += h3 * t1; acc[3][2] += h3 * t2; acc[3][3] += h3 * t3;
            }
#pragma unroll
            for (int i = 0; i < 4; i++) {
                const int n = n0 + nb + i;
                if (n < N) {
#pragma unroll
                    for (int j = 0; j < 4; j++)
                        if (rb + j < L) qout[n * L + rb + j] = acc[i][j];
                }
            }
        }
    }
}

// ---------------------------------------------------------------------------
// attn_all: R15 + vectorized alpha loads in the weighted-sums phase
// ---------------------------------------------------------------------------
#define MBP 72

__global__ __launch_bounds__(64) void attn_all(
    const int* __restrict__ item_nbr, const int* __restrict__ item_time,
    const int* __restrict__ user_nbr, const int* __restrict__ user_time)
{
    const int b    = blockIdx.x;
    const int tid  = threadIdx.x;
    const int lane = tid & 31;
    const int wid  = tid >> 5;

    int n;
    const __half *src_h, *dst_h;
    const int *nbr, *tim;
    if (b < NI) {
        n = b;  src_h = g_uh;  dst_h = g_ih;
        nbr = item_nbr;  tim = item_time;
    } else {
        n = b - NI;  src_h = g_ih;  dst_h = g_uh;
        nbr = user_nbr;  tim = user_time;
    }
    const float* qrow = g_q + b * L;
    __half* mrow = g_m + b * KMP;

    __shared__ __align__(16) __half mb[L][MBP];
    __shared__ __align__(16) __half hh[D];
    __shared__ __align__(16) int    ks[64];     // packed keys: time*64 + idx
    __shared__ float   qs[L];                   // prefetched q row
    __shared__ float   ee[L], e1[L];
    __shared__ __align__(16) __half2 eep[52];   // duplicated-alpha pairs (pad 52)
    __shared__ __align__(16) __half2 e1p[52];
    __shared__ int     nbs[L], ro[L];
    __shared__ int     s_last;

    if (tid < 32) ((__half2*)hh)[tid] = ((const __half2*)(dst_h + n * D))[tid];
    if (tid < L) {
        ks[tid]  = tim[n * L + tid] * 64 + tid;
        nbs[tid] = nbr[n * L + tid];
        qs[tid]  = qrow[tid];                   // hide L2 latency under gather
    } else {
        ks[tid] = 0x7fffffff;                   // pad: counts as >= any key
    }
    __syncthreads();

    // gather mailbox (8B loads, 8B stores, 4 rows per pass; MLP=13)
    {
        const int lane4 = tid & 15, row4 = tid >> 4;
#pragma unroll
        for (int l0 = 0; l0 < 48; l0 += 4) {
            const int l = l0 + row4;
            const uint2 val = *((const uint2*)(src_h + nbs[l] * D) + lane4);
            *(uint2*)&mb[l][lane4 * 4] = val;
        }
        if (row4 < 2) {
            const int l = 48 + row4;
            const uint2 val = *((const uint2*)(src_h + nbs[l] * D) + lane4);
            *(uint2*)&mb[l][lane4 * 4] = val;
        }
    }

    // ranks: packed keys, strict < == stable (time, idx) order
    if (tid < L) {
        const int k = ks[tid];
        int r = 0;
#pragma unroll
        for (int jb = 0; jb < 13; jb++) {
            const int4 v = ((const int4*)ks)[jb];
            r += (v.x < k) + (v.y < k) + (v.z < k) + (v.w < k);
        }
        ro[tid] = L - 1 - r;
    }
    // argmax (first index of max): max of key^63 flips tie-break to lowest idx
    if (wid == 0) {
        int bv = ks[lane] ^ 63;
        if (lane < L - 32) bv = max(bv, ks[lane + 32] ^ 63);
#pragma unroll
        for (int o = 16; o > 0; o >>= 1)
            bv = max(bv, __shfl_xor_sync(0xffffffffu, bv, o));
        if (lane == 0) s_last = (bv & 63) ^ 63;
    }
    __syncthreads();

    // logits: hfma2 on 16B LDS rows
    if (tid < L) {
        const uint4* rowp  = (const uint4*)&mb[tid][0];
        const uint4* lastp = (const uint4*)&mb[s_last][0];
        const uint4* hp    = (const uint4*)hh;
        __half2 sa = __float2half2_rn(0.f), sb = sa, ta = sa, tb = sa;
#pragma unroll
        for (int i = 0; i < 8; i++) {
            const uint4 rv = rowp[i], lv = lastp[i], hv = hp[i];
            const __half2 r0 = *(const __half2*)&rv.x, r1 = *(const __half2*)&rv.y;
            const __half2 r2 = *(const __half2*)&rv.z, r3 = *(const __half2*)&rv.w;
            const __half2 l0 = *(const __half2*)&lv.x, l1 = *(const __half2*)&lv.y;
            const __half2 l2 = *(const __half2*)&lv.z, l3 = *(const __half2*)&lv.w;
            const __half2 h0 = *(const __half2*)&hv.x, h1 = *(const __half2*)&hv.y;
            const __half2 h2 = *(const __half2*)&hv.z, h3 = *(const __half2*)&hv.w;
            sa = __hfma2(r0, h0, sa); sb = __hfma2(r1, h1, sb);
            sa = __hfma2(r2, h2, sa); sb = __hfma2(r3, h3, sb);
            ta = __hfma2(r0, l0, ta); tb = __hfma2(r1, l1, tb);
            ta = __hfma2(r2, l2, ta); tb = __hfma2(r3, l3, tb);
        }
        const float s  = __low2float(sa) + __high2float(sa)
                       + __low2float(sb) + __high2float(sb);
        const float s1 = __low2float(ta) + __high2float(ta)
                       + __low2float(tb) + __high2float(tb);
        ee[tid] = (s + qs[ro[tid]]) * 0.125f;
        e1[tid] = s1 * 0.125f;
    }
    __syncthreads();

    // two softmaxes over L (warp 0); emit duplicated half2 alphas
    if (wid == 0) {
        float m = -1e30f, m1 = -1e30f;
        for (int l = lane; l < L; l += 32) {
            m  = fmaxf(m,  ee[l]);
            m1 = fmaxf(m1, e1[l]);
        }
#pragma unroll
        for (int o = 16; o > 0; o >>= 1) {
            m  = fmaxf(m,  __shfl_xor_sync(0xffffffffu, m,  o));
            m1 = fmaxf(m1, __shfl_xor_sync(0xffffffffu, m1, o));
        }
        float s = 0.f, s1 = 0.f;
        for (int l = lane; l < L; l += 32) {
            const float a  = __expf(ee[l] - m);
            const float a1 = __expf(e1[l] - m1);
            ee[l] = a;  e1[l] = a1;
            s += a;  s1 += a1;
        }
#pragma unroll
        for (int o = 16; o > 0; o >>= 1) {
            s  += __shfl_xor_sync(0xffffffffu, s,  o);
            s1 += __shfl_xor_sync(0xffffffffu, s1, o);
        }
        const float inv = 1.f / s, inv1 = 1.f / s1;
        for (int l = lane; l < L; l += 32) {
            const float a  = ee[l] * inv;
            const float a1 = e1[l] * inv1;
            ee[l] = a;
            eep[l] = __half2half2(__float2half(a));
            e1p[l] = __half2half2(__float2half(a1));
        }
        if (lane < 2) {     // zero pad l=50,51 so uint4 reads are safe
            eep[L + lane] = __float2half2_rn(0.f);
            e1p[L + lane] = __float2half2_rn(0.f);
        }
    }
    __syncthreads();

    // weighted mailbox sums: warp0; alphas loaded 4-at-a-time via LDS.128
    if (tid < 32) {
        __half2 al0 = __float2half2_rn(0.f), al1 = al0, as0 = al0, as1 = al0;
#pragma unroll
        for (int l = 0; l < 52; l += 4) {
            const uint4 av = *(const uint4*)&eep[l];
            const uint4 bv = *(const uint4*)&e1p[l];
            const __half2 m0 = *(const __half2*)&mb[l][2 * tid];
            const __half2 m1 = (l + 1 < L) ? *(const __half2*)&mb[l + 1][2 * tid] : __float2half2_rn(0.f);
            const __half2 m2 = (l + 2 < L) ? *(const __half2*)&mb[l + 2][2 * tid] : __float2half2_rn(0.f);
            const __half2 m3 = (l + 3 < L) ? *(const __half2*)&mb[l + 3][2 * tid] : __float2half2_rn(0.f);
            al0 = __hfma2(*(const __half2*)&av.x, m0, al0);
            as0 = __hfma2(*(const __half2*)&bv.x, m0, as0);
            al1 = __hfma2(*(const __half2*)&av.y, m1, al1);
            as1 = __hfma2(*(const __half2*)&bv.y, m1, as1);
            al0 = __hfma2(*(const __half2*)&av.z, m2, al0);
            as0 = __hfma2(*(const __half2*)&bv.z, m2, as0);
            al1 = __hfma2(*(const __half2*)&av.w, m3, al1);
            as1 = __hfma2(*(const __half2*)&bv.w, m3, as1);
        }
        *(__half2*)&mrow[2 * tid]     = __hadd2(al0, al1);
        *(__half2*)&mrow[D + 2 * tid] = __hadd2(as0, as1);
    }
    if (tid < L) mrow[2 * D + ro[tid]] = __float2half(ee[tid]);
    else         mrow[2 * D + tid]     = __half(0.f);   // pad 178..191
}

// ---------------------------------------------------------------------------
// epilogue (HMMA, R15 exact): 32 nodes x 64 cols, 128 threads, As/ot unioned.
// ---------------------------------------------------------------------------
#define ASTR 208   // smem A row stride in halves (416B, 16B-aligned)

__global__ __launch_bounds__(128) void epilogue(
    const float* __restrict__ user_feat, const float* __restrict__ item_feat,
    float* __restrict__ user_out,        float* __restrict__ item_out)
{
    const bool item = blockIdx.x < EIB;
    const int  nb   = item ? blockIdx.x * 32 : NI + (blockIdx.x - EIB) * 32;
    const __half* Wc  = g_wch[item ? 0 : 1];
    const float* feat = item ? item_feat : user_feat;
    float* out        = item ? item_out  : user_out;
    const int base    = item ? nb : nb - NI;
    const int Nloc    = item ? NI : NU;

    __shared__ __align__(16) char smem_buf[32 * ASTR * sizeof(__half)];
    __half* As = (__half*)smem_buf;
    float*  ot = (float*)smem_buf;

    const int t = threadIdx.x, w = t >> 5;
    const int rt  = w >> 1;          // row tile 0..1
    const int ct0 = (w & 1) * 2;     // col tiles ct0, ct0+1

    {
        const __half* asrc = g_m + (size_t)nb * KMP;
#pragma unroll
        for (int i = t; i < 32 * (KMP / 8); i += 128) {
            const int row = i / (KMP / 8), c8 = i % (KMP / 8);
            *(float4*)&As[row * ASTR + c8 * 8] =
                *(const float4*)&asrc[row * KMP + c8 * 8];
        }
    }
    __syncthreads();

    wmma::fragment<wmma::accumulator, 16, 16, 16, float> acc0, acc1;
    wmma::fill_fragment(acc0, 0.f);
    wmma::fill_fragment(acc1, 0.f);

    wmma::fragment<wmma::matrix_b, 16, 16, 16, __half, wmma::row_major> bf0, bf1;
    wmma::load_matrix_sync(bf0, Wc + ct0 * 16, D);
    wmma::load_matrix_sync(bf1, Wc + (ct0 + 1) * 16, D);

#pragma unroll
    for (int kt = 0; kt < KMP / 16; kt++) {
        wmma::fragment<wmma::matrix_a, 16, 16, 16, __half, wmma::row_major> af;
        wmma::load_matrix_sync(af, &As[(rt * 16) * ASTR + kt * 16], ASTR);
        wmma::mma_sync(acc0, af, bf0, acc0);
        wmma::mma_sync(acc1, af, bf1, acc1);
        if (kt + 1 < KMP / 16) {
            wmma::load_matrix_sync(bf0, Wc + (kt + 1) * 16 * D + ct0 * 16, D);
            wmma::load_matrix_sync(bf1, Wc + (kt + 1) * 16 * D + (ct0 + 1) * 16, D);
        }
    }
    __syncthreads();   // ALL warps done reading As before ot overwrites it
    wmma::store_matrix_sync(&ot[(rt * 16) * 72 + ct0 * 16],       acc0, 72, wmma::mem_row_major);
    wmma::store_matrix_sync(&ot[(rt * 16) * 72 + (ct0 + 1) * 16], acc1, 72, wmma::mem_row_major);
    __syncthreads();

    const int col = (t & 15) * 4, r0 = t >> 4;   // r0: 0..7
#pragma unroll
    for (int i = 0; i < 4; i++) {
        const int row = r0 + i * 8;
        const int nl  = base + row;
        if (nl < Nloc) {
            const float4 fv = *(const float4*)&feat[nl * D + col];
            const float4 av = *(const float4*)&ot[row * 72 + col];
            float4 r;
            r.x = av.x + fv.x;  r.x = r.x > 0.f ? r.x : expm1f(r.x);
            r.y = av.y + fv.y;  r.y = r.y > 0.f ? r.y : expm1f(r.y);
            r.z = av.z + fv.z;  r.z = r.z > 0.f ? r.z : expm1f(r.z);
            r.w = av.w + fv.w;  r.w = r.w > 0.f ? r.w : expm1f(r.w);
            *(float4*)&out[nl * D + col] = r;
        }
    }
}

// ---------------------------------------------------------------------------
extern "C" void kernel_launch(void* const* d_in, const int* in_sizes, int n_in,
                              void* d_out, int out_size) {
    const float* user_feat = (const float*)d_in[0];
    const float* item_feat = (const float*)d_in[1];
    const float* W_u       = (const float*)d_in[2];
    const float* W_i       = (const float*)d_in[3];
    const float* Wg_u      = (const float*)d_in[4];
    const float* Wg_i      = (const float*)d_in[5];
    const float* i_te      = (const float*)d_in[6];
    const float* i_te_k    = (const float*)d_in[7];
    const float* u_te      = (const float*)d_in[8];
    const float* u_te_k    = (const float*)d_in[9];
    const int*   item_nbr  = (const int*)d_in[10];
    const int*   item_time = (const int*)d_in[11];
    const int*   user_nbr  = (const int*)d_in[12];
    const int*   user_time = (const int*)d_in[13];

    float* user_out = (float*)d_out;            // [NU, D]
    float* item_out = (float*)d_out + NU * D;   // [NI, D]

    prep<<<16, 256>>>(Wg_i, i_te_k, Wg_u, u_te_k, i_te, u_te, W_i, W_u);
    projq<<<PB + QB, 256>>>(user_feat, item_feat, W_u, W_i);
    attn_all<<<NT, 64>>>(item_nbr, item_time, user_nbr, user_time);
    epilogue<<<EIB + EUB, 128>>>(user_feat, item_feat, user_out, item_out);
}